// round 1
// baseline (speedup 1.0000x reference)
#include <cuda_runtime.h>
#include <cuda_bf16.h>

// Problem constants
#define BATCH 4
#define SEQ   2048
#define HID   768
#define NHEAD 12
#define HDIM  64
#define QKV3  (3 * HID)   // 2304

// Scratch (allocation-free: __device__ globals)
__device__ float g_qkv[(long)BATCH * SEQ * QKV3];   // [B,S,3H]  75.5 MB
__device__ float g_attn[(long)BATCH * SEQ * HID];   // [B,S,H]   25.2 MB

// ---------------------------------------------------------------------------
// SGEMM: C[M,N] = A[M,K] @ B[K,N], all row-major fp32.
// 128x128 block tile, BK=8, 256 threads, 8x8 register tile per thread.
// Requires M%128==0, N%128==0, K%8==0 (true for all our shapes).
// ---------------------------------------------------------------------------
#define GBM 128
#define GBN 128
#define GBK 8
#define GTM 8
#define GTN 8

__global__ __launch_bounds__(256, 2)
void sgemm_kernel(const float* __restrict__ A, const float* __restrict__ B,
                  float* __restrict__ C, int M, int N, int K)
{
    __shared__ float As[GBK][GBM];   // A tile, transposed on load
    __shared__ float Bs[GBK][GBN];

    const int bx = blockIdx.x;   // N tile
    const int by = blockIdx.y;   // M tile
    const int tid = threadIdx.x;
    const int tx = tid & 15;     // 0..15 -> N
    const int ty = tid >> 4;     // 0..15 -> M

    const float* Ab = A + (long)(by * GBM) * K;
    const float* Bb = B + bx * GBN;

    // A tile load mapping: 128 rows x 8 cols -> one float4 per (thread pair)
    const int arow  = tid >> 1;          // 0..127
    const int acol4 = (tid & 1) * 4;     // 0 or 4
    // B tile load mapping: 8 rows x 128 cols, fully coalesced
    const int brow  = tid >> 5;          // 0..7
    const int bcol4 = (tid & 31) * 4;    // 0..124

    float acc[GTM][GTN];
    #pragma unroll
    for (int i = 0; i < GTM; i++)
        #pragma unroll
        for (int j = 0; j < GTN; j++) acc[i][j] = 0.f;

    for (int k0 = 0; k0 < K; k0 += GBK) {
        float4 av = *(const float4*)&Ab[(long)arow * K + k0 + acol4];
        As[acol4 + 0][arow] = av.x;
        As[acol4 + 1][arow] = av.y;
        As[acol4 + 2][arow] = av.z;
        As[acol4 + 3][arow] = av.w;
        *(float4*)&Bs[brow][bcol4] = *(const float4*)&Bb[(long)(k0 + brow) * N + bcol4];
        __syncthreads();

        #pragma unroll
        for (int kk = 0; kk < GBK; kk++) {
            float4 a0 = *(const float4*)&As[kk][ty * GTM];
            float4 a1 = *(const float4*)&As[kk][ty * GTM + 4];
            float4 b0 = *(const float4*)&Bs[kk][tx * GTN];
            float4 b1 = *(const float4*)&Bs[kk][tx * GTN + 4];
            float a[GTM] = {a0.x, a0.y, a0.z, a0.w, a1.x, a1.y, a1.z, a1.w};
            float b[GTN] = {b0.x, b0.y, b0.z, b0.w, b1.x, b1.y, b1.z, b1.w};
            #pragma unroll
            for (int i = 0; i < GTM; i++)
                #pragma unroll
                for (int j = 0; j < GTN; j++)
                    acc[i][j] = fmaf(a[i], b[j], acc[i][j]);
        }
        __syncthreads();
    }

    #pragma unroll
    for (int i = 0; i < GTM; i++) {
        long row = (long)(by * GBM + ty * GTM + i);
        float* Crow = C + row * N + bx * GBN + tx * GTN;
        *(float4*)&Crow[0] = make_float4(acc[i][0], acc[i][1], acc[i][2], acc[i][3]);
        *(float4*)&Crow[4] = make_float4(acc[i][4], acc[i][5], acc[i][6], acc[i][7]);
    }
}

// ---------------------------------------------------------------------------
// Flash attention (causal), fp32, online softmax.
// Grid: (qtile=32, head=12, batch=4).  Block: 256 threads (16x16).
// 64 q-rows x 64 k-cols per iteration, HDIM=64.
// Thread (tx,ty) owns S/P rows ty*4+i, cols tx*4+j, and O rows ty*4+i, dims tx*4+j.
// ---------------------------------------------------------------------------
#define ABM 64
#define ABN 64
#define APITCH 68           // row pitch in floats (pad 4 keeps float4 alignment)
#define FLASH_SMEM_FLOATS (4 * HDIM * APITCH)
#define FLASH_SMEM_BYTES  (FLASH_SMEM_FLOATS * 4)

__global__ __launch_bounds__(256, 1)
void flash_attn_kernel(const float* __restrict__ qkv, float* __restrict__ out)
{
    extern __shared__ float smem[];
    float* Qt = smem;                       // [HDIM][APITCH]  Q transposed: Qt[d][r]
    float* Kt = Qt + HDIM * APITCH;         // [HDIM][APITCH]  K transposed: Kt[d][c]
    float* Vs = Kt + HDIM * APITCH;         // [ABN][APITCH]   V: Vs[c][d]
    float* Pt = Vs + ABN * APITCH;          // [ABN][APITCH]   P transposed: Pt[c][r]

    const int qt = blockIdx.x;
    const int h  = blockIdx.y;
    const int b  = blockIdx.z;
    const int tid = threadIdx.x;
    const int tx = tid & 15;
    const int ty = tid >> 4;

    const long rowstride = QKV3;
    const float* qbase = qkv + (long)b * SEQ * QKV3 + h * HDIM;            // Q cols
    const float* kbase = qbase + HID;                                       // K cols
    const float* vbase = qbase + 2 * HID;                                   // V cols

    // Load Q tile transposed: rows qt*64..+63, dims 0..63
    for (int i = tid; i < ABM * (HDIM / 4); i += 256) {
        int r  = i >> 4;          // 0..63
        int d4 = (i & 15) * 4;    // 0..60
        float4 v = *(const float4*)&qbase[(long)(qt * ABM + r) * rowstride + d4];
        Qt[(d4 + 0) * APITCH + r] = v.x;
        Qt[(d4 + 1) * APITCH + r] = v.y;
        Qt[(d4 + 2) * APITCH + r] = v.z;
        Qt[(d4 + 3) * APITCH + r] = v.w;
    }

    float m_i[4], l_i[4], o[4][4];
    #pragma unroll
    for (int i = 0; i < 4; i++) {
        m_i[i] = -1e30f; l_i[i] = 0.f;
        #pragma unroll
        for (int j = 0; j < 4; j++) o[i][j] = 0.f;
    }

    const float scale = 0.125f;  // 1/sqrt(64)

    for (int kt = 0; kt <= qt; kt++) {
        __syncthreads();   // protect Kt/Vs/Pt from previous iteration readers
        // Load K tile transposed, V tile natural
        for (int i = tid; i < ABN * (HDIM / 4); i += 256) {
            int c  = i >> 4;
            int d4 = (i & 15) * 4;
            float4 kv4 = *(const float4*)&kbase[(long)(kt * ABN + c) * rowstride + d4];
            Kt[(d4 + 0) * APITCH + c] = kv4.x;
            Kt[(d4 + 1) * APITCH + c] = kv4.y;
            Kt[(d4 + 2) * APITCH + c] = kv4.z;
            Kt[(d4 + 3) * APITCH + c] = kv4.w;
            float4 vv4 = *(const float4*)&vbase[(long)(kt * ABN + c) * rowstride + d4];
            *(float4*)&Vs[c * APITCH + d4] = vv4;
        }
        __syncthreads();

        // S = Q @ K^T * scale
        float s[4][4];
        #pragma unroll
        for (int i = 0; i < 4; i++)
            #pragma unroll
            for (int j = 0; j < 4; j++) s[i][j] = 0.f;

        #pragma unroll 8
        for (int d = 0; d < HDIM; d++) {
            float4 aq = *(const float4*)&Qt[d * APITCH + ty * 4];
            float4 bk = *(const float4*)&Kt[d * APITCH + tx * 4];
            float a[4] = {aq.x, aq.y, aq.z, aq.w};
            float bb[4] = {bk.x, bk.y, bk.z, bk.w};
            #pragma unroll
            for (int i = 0; i < 4; i++)
                #pragma unroll
                for (int j = 0; j < 4; j++)
                    s[i][j] = fmaf(a[i], bb[j], s[i][j]);
        }

        // causal mask (only diagonal tile needs it)
        if (kt == qt) {
            #pragma unroll
            for (int i = 0; i < 4; i++)
                #pragma unroll
                for (int j = 0; j < 4; j++)
                    if (tx * 4 + j > ty * 4 + i) s[i][j] = -1e30f;
            #pragma unroll
            for (int i = 0; i < 4; i++)
                #pragma unroll
                for (int j = 0; j < 4; j++) if (s[i][j] > -1e29f) s[i][j] *= scale;
        } else {
            #pragma unroll
            for (int i = 0; i < 4; i++)
                #pragma unroll
                for (int j = 0; j < 4; j++) s[i][j] *= scale;
        }

        // Online softmax per row; 16-lane (same-ty) shfl reductions
        #pragma unroll
        for (int i = 0; i < 4; i++) {
            float rmax = s[i][0];
            #pragma unroll
            for (int j = 1; j < 4; j++) rmax = fmaxf(rmax, s[i][j]);
            #pragma unroll
            for (int mk = 8; mk >= 1; mk >>= 1)
                rmax = fmaxf(rmax, __shfl_xor_sync(0xffffffffu, rmax, mk));
            float mnew  = fmaxf(m_i[i], rmax);
            float alpha = __expf(m_i[i] - mnew);
            float rsum = 0.f;
            #pragma unroll
            for (int j = 0; j < 4; j++) {
                float p = __expf(s[i][j] - mnew);
                Pt[(tx * 4 + j) * APITCH + ty * 4 + i] = p;
                rsum += p;
            }
            #pragma unroll
            for (int mk = 8; mk >= 1; mk >>= 1)
                rsum += __shfl_xor_sync(0xffffffffu, rsum, mk);
            l_i[i] = l_i[i] * alpha + rsum;
            m_i[i] = mnew;
            #pragma unroll
            for (int j = 0; j < 4; j++) o[i][j] *= alpha;
        }
        __syncthreads();

        // O += P @ V
        #pragma unroll 8
        for (int c = 0; c < ABN; c++) {
            float4 ap = *(const float4*)&Pt[c * APITCH + ty * 4];
            float4 bv = *(const float4*)&Vs[c * APITCH + tx * 4];
            float a[4] = {ap.x, ap.y, ap.z, ap.w};
            float bb[4] = {bv.x, bv.y, bv.z, bv.w};
            #pragma unroll
            for (int i = 0; i < 4; i++)
                #pragma unroll
                for (int j = 0; j < 4; j++)
                    o[i][j] = fmaf(a[i], bb[j], o[i][j]);
        }
    }

    // Epilogue: normalize and write [B,S,NH,HD] == [B,S,H]
    #pragma unroll
    for (int i = 0; i < 4; i++) {
        float inv = 1.f / l_i[i];
        long row = (long)b * SEQ + qt * ABM + ty * 4 + i;
        float* dst = out + row * HID + h * HDIM + tx * 4;
        *(float4*)dst = make_float4(o[i][0] * inv, o[i][1] * inv,
                                    o[i][2] * inv, o[i][3] * inv);
    }
}

// ---------------------------------------------------------------------------
// Launch
// ---------------------------------------------------------------------------
extern "C" void kernel_launch(void* const* d_in, const int* in_sizes, int n_in,
                              void* d_out, int out_size)
{
    const float* x     = (const float*)d_in[0];
    const float* w_qkv = (const float*)d_in[1];
    const float* w_out = (const float*)d_in[2];
    float* out = (float*)d_out;

    float *qkv, *attn;
    cudaGetSymbolAddress((void**)&qkv, g_qkv);
    cudaGetSymbolAddress((void**)&attn, g_attn);

    const int M = BATCH * SEQ;   // 8192

    // 1) QKV projection: [8192,768] @ [768,2304]
    sgemm_kernel<<<dim3(QKV3 / GBN, M / GBM), 256>>>(x, w_qkv, qkv, M, QKV3, HID);

    // 2) Causal flash attention
    cudaFuncSetAttribute(flash_attn_kernel,
                         cudaFuncAttributeMaxDynamicSharedMemorySize, FLASH_SMEM_BYTES);
    flash_attn_kernel<<<dim3(SEQ / ABM, NHEAD, BATCH), 256, FLASH_SMEM_BYTES>>>(qkv, attn);

    // 3) Output projection: [8192,768] @ [768,768]
    sgemm_kernel<<<dim3(HID / GBN, M / GBM), 256>>>(attn, w_out, out, M, HID, HID);
}

// round 3
// speedup vs baseline: 1.4092x; 1.4092x over previous
#include <cuda_runtime.h>
#include <cuda_bf16.h>
#include <cstdint>

// Problem constants
#define BATCH 4
#define SEQ   2048
#define HID   768
#define NHEAD 12
#define HDIM  64
#define QKV3  2304
#define KDIM  768

// Scratch (allocation-free: __device__ globals)
__device__ float g_qkv[(long)BATCH * SEQ * QKV3];    // [B,S,3H]
__device__ float g_attn[(long)BATCH * SEQ * HID];    // [B,S,H] (tf32-rounded)
__device__ float g_xc[(long)BATCH * SEQ * HID];      // x, tf32-rounded
__device__ float g_wqkvc[(long)KDIM * QKV3];         // w_qkv, tf32-rounded [K][N]
__device__ float g_woutc[(long)KDIM * HID];          // w_out, tf32-rounded [K][N]

// ---------------------------------------------------------------------------
// Helpers
// ---------------------------------------------------------------------------
__device__ __forceinline__ uint32_t smem_u32(const void* p) {
    uint32_t a;
    asm("{ .reg .u64 t; cvta.to.shared.u64 t, %1; cvt.u32.u64 %0, t; }" : "=r"(a) : "l"(p));
    return a;
}
__device__ __forceinline__ float cvt_tf32(float x) {
    float r;
    asm("cvt.rna.tf32.f32 %0, %1;" : "=f"(r) : "f"(x));
    return r;
}
__device__ __forceinline__ void cp16(uint32_t dst, const void* src) {
    asm volatile("cp.async.cg.shared.global [%0], [%1], 16;" :: "r"(dst), "l"(src) : "memory");
}
__device__ __forceinline__ void cp_commit() {
    asm volatile("cp.async.commit_group;" ::: "memory");
}
__device__ __forceinline__ void cp_wait1() {
    asm volatile("cp.async.wait_group 1;" ::: "memory");
}
__device__ __forceinline__ void cp_wait0() {
    asm volatile("cp.async.wait_group 0;" ::: "memory");
}
__device__ __forceinline__ uint32_t ldsu(uint32_t addr) {
    uint32_t v;
    asm volatile("ld.shared.b32 %0, [%1];" : "=r"(v) : "r"(addr));
    return v;
}
__device__ __forceinline__ void mma_tf32(float* c, const uint32_t* a, const uint32_t* b) {
    asm volatile(
        "mma.sync.aligned.m16n8k8.row.col.f32.tf32.tf32.f32 "
        "{%0,%1,%2,%3}, {%4,%5,%6,%7}, {%8,%9}, {%0,%1,%2,%3};"
        : "+f"(c[0]), "+f"(c[1]), "+f"(c[2]), "+f"(c[3])
        : "r"(a[0]), "r"(a[1]), "r"(a[2]), "r"(a[3]), "r"(b[0]), "r"(b[1]));
}

// ---------------------------------------------------------------------------
// tf32 mma.sync GEMM: C[M,N] = A[M,K] @ B[K,N], row-major, inputs pre-rounded
// to tf32. CTA tile 128x128, K chunk 32, double-buffered cp.async.
// 8 warps: warpM=wid>>2 (x64 rows), warpN=wid&3 (x32 cols).
// SMEM: As[128][36] (pad->conflict-free frag loads), Bs[32][132].
// ---------------------------------------------------------------------------
#define AS_BYTES (128 * 36 * 4)   // 18432
#define BS_BYTES (32 * 132 * 4)   // 16896
#define STAGE_BYTES (AS_BYTES + BS_BYTES)
#define GEMM_SMEM_BYTES (2 * STAGE_BYTES)   // 70656

__global__ __launch_bounds__(256, 2)
void gemm_tf32(const float* __restrict__ A, const float* __restrict__ B,
               float* __restrict__ C, int M, int N, int K)
{
    extern __shared__ char smem[];
    const uint32_t sb = smem_u32(smem);
    const uint32_t AS[2] = { sb, sb + STAGE_BYTES };
    const uint32_t BS[2] = { sb + AS_BYTES, sb + STAGE_BYTES + AS_BYTES };

    const int tid = threadIdx.x;
    const int wid = tid >> 5, lane = tid & 31;
    const int g = lane >> 2, l4 = lane & 3;
    const int warpM = wid >> 2, warpN = wid & 3;
    const int m0 = blockIdx.y * 128, n0 = blockIdx.x * 128;

    // cp.async load mapping
    const int ar = tid >> 1;                 // A row 0..127
    const int ah = (tid & 1) * 64;           // byte offset within A row (2 halves x 64B)
    const int bkr = tid >> 3;                // B k-row 0..31
    const int bseg = (tid & 7) * 64;         // byte offset within B row (8 segs x 64B)

    const float* Ag = A + (long)(m0 + ar) * K;
    const float* Bg = B + n0;

    const int nch = K / 32;

    float c[4][4][4];
    #pragma unroll
    for (int mt = 0; mt < 4; mt++)
        #pragma unroll
        for (int nt = 0; nt < 4; nt++)
            #pragma unroll
            for (int r = 0; r < 4; r++) c[mt][nt][r] = 0.f;

    auto issue = [&](int chunk, int s) {
        const int k0 = chunk * 32;
        const float* asrc = Ag + k0 + (ah >> 2);
        uint32_t adst = AS[s] + ar * 144 + ah;
        #pragma unroll
        for (int q = 0; q < 4; q++) cp16(adst + q * 16, asrc + q * 4);
        const float* bsrc = Bg + (long)(k0 + bkr) * N + (bseg >> 2);
        uint32_t bdst = BS[s] + bkr * 528 + bseg;
        #pragma unroll
        for (int q = 0; q < 4; q++) cp16(bdst + q * 16, bsrc + q * 4);
    };

    issue(0, 0); cp_commit();
    issue(1, 1); cp_commit();

    #pragma unroll 1
    for (int i = 0; i < nch; i++) {
        const int s = i & 1;
        if (i + 2 < nch) cp_wait1(); else cp_wait0();
        __syncthreads();

        #pragma unroll
        for (int ks = 0; ks < 4; ks++) {
            uint32_t af[4][4], bf[4][2];
            #pragma unroll
            for (int mt = 0; mt < 4; mt++) {
                uint32_t base = AS[s] + (uint32_t)((warpM * 64 + mt * 16 + g) * 144
                                                  + ks * 32 + l4 * 4);
                af[mt][0] = ldsu(base);
                af[mt][1] = ldsu(base + 8 * 144);
                af[mt][2] = ldsu(base + 16);
                af[mt][3] = ldsu(base + 8 * 144 + 16);
            }
            #pragma unroll
            for (int nt = 0; nt < 4; nt++) {
                uint32_t base = BS[s] + (uint32_t)((ks * 8 + l4) * 528
                                                  + (warpN * 32 + nt * 8 + g) * 4);
                bf[nt][0] = ldsu(base);
                bf[nt][1] = ldsu(base + 4 * 528);
            }
            #pragma unroll
            for (int mt = 0; mt < 4; mt++)
                #pragma unroll
                for (int nt = 0; nt < 4; nt++)
                    mma_tf32(c[mt][nt], af[mt], bf[nt]);
        }
        __syncthreads();
        if (i + 2 < nch) { issue(i + 2, s); cp_commit(); }
    }

    // Epilogue: fragment c -> C.  c0:(g,2l4) c1:(g,2l4+1) c2:(g+8,2l4) c3:(g+8,2l4+1)
    #pragma unroll
    for (int mt = 0; mt < 4; mt++) {
        #pragma unroll
        for (int nt = 0; nt < 4; nt++) {
            const long row0 = (long)(m0 + warpM * 64 + mt * 16 + g);
            const int col = n0 + warpN * 32 + nt * 8 + l4 * 2;
            *(float2*)&C[row0 * N + col] = make_float2(c[mt][nt][0], c[mt][nt][1]);
            *(float2*)&C[(row0 + 8) * N + col] = make_float2(c[mt][nt][2], c[mt][nt][3]);
        }
    }
}

// ---------------------------------------------------------------------------
// Elementwise tf32 rounding (prep)
// ---------------------------------------------------------------------------
__global__ void cvt_tf32_kernel(const float* __restrict__ in, float* __restrict__ out,
                                int n4)
{
    int i = blockIdx.x * blockDim.x + threadIdx.x;
    if (i < n4) {
        float4 v = ((const float4*)in)[i];
        v.x = cvt_tf32(v.x); v.y = cvt_tf32(v.y);
        v.z = cvt_tf32(v.z); v.w = cvt_tf32(v.w);
        ((float4*)out)[i] = v;
    }
}

// ---------------------------------------------------------------------------
// Flash attention (causal), fp32 SIMT, online softmax (unchanged from R1,
// except epilogue tf32-rounds output to feed the tf32 out-projection).
// ---------------------------------------------------------------------------
#define ABM 64
#define ABN 64
#define APITCH 68
#define FLASH_SMEM_BYTES (4 * HDIM * APITCH * 4)

__global__ __launch_bounds__(256, 1)
void flash_attn_kernel(const float* __restrict__ qkv, float* __restrict__ out)
{
    extern __shared__ float fsm[];
    float* Qt = fsm;
    float* Kt = Qt + HDIM * APITCH;
    float* Vs = Kt + HDIM * APITCH;
    float* Pt = Vs + ABN * APITCH;

    const int qt = blockIdx.x;
    const int hh = blockIdx.y;
    const int b  = blockIdx.z;
    const int tid = threadIdx.x;
    const int tx = tid & 15;
    const int ty = tid >> 4;

    const long rowstride = QKV3;
    const float* qbase = qkv + (long)b * SEQ * QKV3 + hh * HDIM;
    const float* kbase = qbase + HID;
    const float* vbase = qbase + 2 * HID;

    for (int i = tid; i < ABM * (HDIM / 4); i += 256) {
        int rr = i >> 4;
        int d4 = (i & 15) * 4;
        float4 v = *(const float4*)&qbase[(long)(qt * ABM + rr) * rowstride + d4];
        Qt[(d4 + 0) * APITCH + rr] = v.x;
        Qt[(d4 + 1) * APITCH + rr] = v.y;
        Qt[(d4 + 2) * APITCH + rr] = v.z;
        Qt[(d4 + 3) * APITCH + rr] = v.w;
    }

    float m_i[4], l_i[4], o[4][4];
    #pragma unroll
    for (int i = 0; i < 4; i++) {
        m_i[i] = -1e30f; l_i[i] = 0.f;
        #pragma unroll
        for (int j = 0; j < 4; j++) o[i][j] = 0.f;
    }

    const float scale = 0.125f;

    for (int kt = 0; kt <= qt; kt++) {
        __syncthreads();
        for (int i = tid; i < ABN * (HDIM / 4); i += 256) {
            int cc = i >> 4;
            int d4 = (i & 15) * 4;
            float4 kv4 = *(const float4*)&kbase[(long)(kt * ABN + cc) * rowstride + d4];
            Kt[(d4 + 0) * APITCH + cc] = kv4.x;
            Kt[(d4 + 1) * APITCH + cc] = kv4.y;
            Kt[(d4 + 2) * APITCH + cc] = kv4.z;
            Kt[(d4 + 3) * APITCH + cc] = kv4.w;
            float4 vv4 = *(const float4*)&vbase[(long)(kt * ABN + cc) * rowstride + d4];
            *(float4*)&Vs[cc * APITCH + d4] = vv4;
        }
        __syncthreads();

        float s[4][4];
        #pragma unroll
        for (int i = 0; i < 4; i++)
            #pragma unroll
            for (int j = 0; j < 4; j++) s[i][j] = 0.f;

        #pragma unroll 8
        for (int d = 0; d < HDIM; d++) {
            float4 aq = *(const float4*)&Qt[d * APITCH + ty * 4];
            float4 bk = *(const float4*)&Kt[d * APITCH + tx * 4];
            float a[4] = {aq.x, aq.y, aq.z, aq.w};
            float bb[4] = {bk.x, bk.y, bk.z, bk.w};
            #pragma unroll
            for (int i = 0; i < 4; i++)
                #pragma unroll
                for (int j = 0; j < 4; j++)
                    s[i][j] = fmaf(a[i], bb[j], s[i][j]);
        }

        if (kt == qt) {
            #pragma unroll
            for (int i = 0; i < 4; i++)
                #pragma unroll
                for (int j = 0; j < 4; j++)
                    if (tx * 4 + j > ty * 4 + i) s[i][j] = -1e30f;
            #pragma unroll
            for (int i = 0; i < 4; i++)
                #pragma unroll
                for (int j = 0; j < 4; j++) if (s[i][j] > -1e29f) s[i][j] *= scale;
        } else {
            #pragma unroll
            for (int i = 0; i < 4; i++)
                #pragma unroll
                for (int j = 0; j < 4; j++) s[i][j] *= scale;
        }

        #pragma unroll
        for (int i = 0; i < 4; i++) {
            float rmax = s[i][0];
            #pragma unroll
            for (int j = 1; j < 4; j++) rmax = fmaxf(rmax, s[i][j]);
            #pragma unroll
            for (int mk = 8; mk >= 1; mk >>= 1)
                rmax = fmaxf(rmax, __shfl_xor_sync(0xffffffffu, rmax, mk));
            float mnew  = fmaxf(m_i[i], rmax);
            float alpha = __expf(m_i[i] - mnew);
            float rsum = 0.f;
            #pragma unroll
            for (int j = 0; j < 4; j++) {
                float p = __expf(s[i][j] - mnew);
                Pt[(tx * 4 + j) * APITCH + ty * 4 + i] = p;
                rsum += p;
            }
            #pragma unroll
            for (int mk = 8; mk >= 1; mk >>= 1)
                rsum += __shfl_xor_sync(0xffffffffu, rsum, mk);
            l_i[i] = l_i[i] * alpha + rsum;
            m_i[i] = mnew;
            #pragma unroll
            for (int j = 0; j < 4; j++) o[i][j] *= alpha;
        }
        __syncthreads();

        #pragma unroll 8
        for (int cc = 0; cc < ABN; cc++) {
            float4 ap = *(const float4*)&Pt[cc * APITCH + ty * 4];
            float4 bv = *(const float4*)&Vs[cc * APITCH + tx * 4];
            float a[4] = {ap.x, ap.y, ap.z, ap.w};
            float bb[4] = {bv.x, bv.y, bv.z, bv.w};
            #pragma unroll
            for (int i = 0; i < 4; i++)
                #pragma unroll
                for (int j = 0; j < 4; j++)
                    o[i][j] = fmaf(a[i], bb[j], o[i][j]);
        }
    }

    #pragma unroll
    for (int i = 0; i < 4; i++) {
        float inv = 1.f / l_i[i];
        long row = (long)b * SEQ + qt * ABM + ty * 4 + i;
        float* dst = out + row * HID + hh * HDIM + tx * 4;
        *(float4*)dst = make_float4(cvt_tf32(o[i][0] * inv), cvt_tf32(o[i][1] * inv),
                                    cvt_tf32(o[i][2] * inv), cvt_tf32(o[i][3] * inv));
    }
}

// ---------------------------------------------------------------------------
// Launch
// ---------------------------------------------------------------------------
extern "C" void kernel_launch(void* const* d_in, const int* in_sizes, int n_in,
                              void* d_out, int out_size)
{
    const float* x     = (const float*)d_in[0];
    const float* w_qkv = (const float*)d_in[1];
    const float* w_out = (const float*)d_in[2];
    float* out = (float*)d_out;

    float *qkv, *attn, *xc, *wqkvc, *woutc;
    cudaGetSymbolAddress((void**)&qkv, g_qkv);
    cudaGetSymbolAddress((void**)&attn, g_attn);
    cudaGetSymbolAddress((void**)&xc, g_xc);
    cudaGetSymbolAddress((void**)&wqkvc, g_wqkvc);
    cudaGetSymbolAddress((void**)&woutc, g_woutc);

    const int M = BATCH * SEQ;   // 8192

    // 0) tf32-round GEMM inputs
    {
        int n4 = (M * HID) / 4;
        cvt_tf32_kernel<<<(n4 + 255) / 256, 256>>>(x, xc, n4);
        n4 = (KDIM * QKV3) / 4;
        cvt_tf32_kernel<<<(n4 + 255) / 256, 256>>>(w_qkv, wqkvc, n4);
        n4 = (KDIM * HID) / 4;
        cvt_tf32_kernel<<<(n4 + 255) / 256, 256>>>(w_out, woutc, n4);
    }

    cudaFuncSetAttribute(gemm_tf32, cudaFuncAttributeMaxDynamicSharedMemorySize,
                         GEMM_SMEM_BYTES);

    // 1) QKV projection: [8192,768] @ [768,2304]
    gemm_tf32<<<dim3(QKV3 / 128, M / 128), 256, GEMM_SMEM_BYTES>>>(xc, wqkvc, qkv,
                                                                   M, QKV3, KDIM);

    // 2) Causal flash attention (fp32 SIMT)
    cudaFuncSetAttribute(flash_attn_kernel,
                         cudaFuncAttributeMaxDynamicSharedMemorySize, FLASH_SMEM_BYTES);
    flash_attn_kernel<<<dim3(SEQ / ABM, NHEAD, BATCH), 256, FLASH_SMEM_BYTES>>>(qkv, attn);

    // 3) Output projection: [8192,768] @ [768,768]
    gemm_tf32<<<dim3(HID / 128, M / 128), 256, GEMM_SMEM_BYTES>>>(attn, woutc, out,
                                                                  M, HID, KDIM);
}

// round 6
// speedup vs baseline: 2.5451x; 1.8060x over previous
#include <cuda_runtime.h>
#include <cuda_bf16.h>
#include <cstdint>

// Problem constants
#define BATCH 4
#define SEQ   2048
#define HID   768
#define NHEAD 12
#define HDIM  64
#define QKV3  2304
#define KDIM  768

// Scratch (allocation-free: __device__ globals)
__device__ float g_qkv[(long)BATCH * SEQ * QKV3];    // [B,S,3H] tf32-rounded
__device__ float g_attn[(long)BATCH * SEQ * HID];    // [B,S,H]  tf32-rounded
__device__ float g_xc[(long)BATCH * SEQ * HID];      // x, tf32-rounded
__device__ float g_wqkvc[(long)KDIM * QKV3];         // w_qkv tf32-rounded [K][N]
__device__ float g_woutc[(long)KDIM * HID];          // w_out tf32-rounded [K][N]

// ---------------------------------------------------------------------------
// Helpers
// ---------------------------------------------------------------------------
__device__ __forceinline__ uint32_t smem_u32(const void* p) {
    uint32_t a;
    asm("{ .reg .u64 t; cvta.to.shared.u64 t, %1; cvt.u32.u64 %0, t; }" : "=r"(a) : "l"(p));
    return a;
}
__device__ __forceinline__ float cvt_tf32(float x) {
    float r;
    asm("cvt.rna.tf32.f32 %0, %1;" : "=f"(r) : "f"(x));
    return r;
}
__device__ __forceinline__ float ex2f(float x) {
    float r;
    asm("ex2.approx.f32 %0, %1;" : "=f"(r) : "f"(x));
    return r;
}
__device__ __forceinline__ void cp16(uint32_t dst, const void* src) {
    asm volatile("cp.async.cg.shared.global [%0], [%1], 16;" :: "r"(dst), "l"(src) : "memory");
}
__device__ __forceinline__ void cp_commit() {
    asm volatile("cp.async.commit_group;" ::: "memory");
}
__device__ __forceinline__ void cp_wait1() {
    asm volatile("cp.async.wait_group 1;" ::: "memory");
}
__device__ __forceinline__ void cp_wait0() {
    asm volatile("cp.async.wait_group 0;" ::: "memory");
}
__device__ __forceinline__ uint32_t ldsu(uint32_t addr) {
    uint32_t v;
    asm volatile("ld.shared.b32 %0, [%1];" : "=r"(v) : "r"(addr));
    return v;
}
__device__ __forceinline__ void sts2(uint32_t addr, float x, float y) {
    asm volatile("st.shared.v2.f32 [%0], {%1, %2};" :: "r"(addr), "f"(x), "f"(y) : "memory");
}
__device__ __forceinline__ void mma_tf32(float* c, const uint32_t* a, const uint32_t* b) {
    asm volatile(
        "mma.sync.aligned.m16n8k8.row.col.f32.tf32.tf32.f32 "
        "{%0,%1,%2,%3}, {%4,%5,%6,%7}, {%8,%9}, {%0,%1,%2,%3};"
        : "+f"(c[0]), "+f"(c[1]), "+f"(c[2]), "+f"(c[3])
        : "r"(a[0]), "r"(a[1]), "r"(a[2]), "r"(a[3]), "r"(b[0]), "r"(b[1]));
}

// ---------------------------------------------------------------------------
// tf32 mma.sync GEMM (from R3, passing). ROUND: tf32-round output (for qkv).
// ---------------------------------------------------------------------------
#define AS_BYTES (128 * 36 * 4)
#define BS_BYTES (32 * 132 * 4)
#define STAGE_BYTES (AS_BYTES + BS_BYTES)
#define GEMM_SMEM_BYTES (2 * STAGE_BYTES)

template <bool ROUND>
__global__ __launch_bounds__(256, 2)
void gemm_tf32(const float* __restrict__ A, const float* __restrict__ B,
               float* __restrict__ C, int M, int N, int K)
{
    extern __shared__ char smem[];
    const uint32_t sb = smem_u32(smem);
    const uint32_t AS[2] = { sb, sb + STAGE_BYTES };
    const uint32_t BS[2] = { sb + AS_BYTES, sb + STAGE_BYTES + AS_BYTES };

    const int tid = threadIdx.x;
    const int wid = tid >> 5, lane = tid & 31;
    const int g = lane >> 2, l4 = lane & 3;
    const int warpM = wid >> 2, warpN = wid & 3;
    const int m0 = blockIdx.y * 128, n0 = blockIdx.x * 128;

    const int ar = tid >> 1;
    const int ah = (tid & 1) * 64;
    const int bkr = tid >> 3;
    const int bseg = (tid & 7) * 64;

    const float* Ag = A + (long)(m0 + ar) * K;
    const float* Bg = B + n0;
    const int nch = K / 32;

    float c[4][4][4];
    #pragma unroll
    for (int mt = 0; mt < 4; mt++)
        #pragma unroll
        for (int nt = 0; nt < 4; nt++)
            #pragma unroll
            for (int r = 0; r < 4; r++) c[mt][nt][r] = 0.f;

    auto issue = [&](int chunk, int s) {
        const int k0 = chunk * 32;
        const float* asrc = Ag + k0 + (ah >> 2);
        uint32_t adst = AS[s] + ar * 144 + ah;
        #pragma unroll
        for (int q = 0; q < 4; q++) cp16(adst + q * 16, asrc + q * 4);
        const float* bsrc = Bg + (long)(k0 + bkr) * N + (bseg >> 2);
        uint32_t bdst = BS[s] + bkr * 528 + bseg;
        #pragma unroll
        for (int q = 0; q < 4; q++) cp16(bdst + q * 16, bsrc + q * 4);
    };

    issue(0, 0); cp_commit();
    issue(1, 1); cp_commit();

    #pragma unroll 1
    for (int i = 0; i < nch; i++) {
        const int s = i & 1;
        if (i + 2 < nch) cp_wait1(); else cp_wait0();
        __syncthreads();

        #pragma unroll
        for (int ks = 0; ks < 4; ks++) {
            uint32_t af[4][4], bf[4][2];
            #pragma unroll
            for (int mt = 0; mt < 4; mt++) {
                uint32_t base = AS[s] + (uint32_t)((warpM * 64 + mt * 16 + g) * 144
                                                  + ks * 32 + l4 * 4);
                af[mt][0] = ldsu(base);
                af[mt][1] = ldsu(base + 8 * 144);
                af[mt][2] = ldsu(base + 16);
                af[mt][3] = ldsu(base + 8 * 144 + 16);
            }
            #pragma unroll
            for (int nt = 0; nt < 4; nt++) {
                uint32_t base = BS[s] + (uint32_t)((ks * 8 + l4) * 528
                                                  + (warpN * 32 + nt * 8 + g) * 4);
                bf[nt][0] = ldsu(base);
                bf[nt][1] = ldsu(base + 4 * 528);
            }
            #pragma unroll
            for (int mt = 0; mt < 4; mt++)
                #pragma unroll
                for (int nt = 0; nt < 4; nt++)
                    mma_tf32(c[mt][nt], af[mt], bf[nt]);
        }
        __syncthreads();
        if (i + 2 < nch) { issue(i + 2, s); cp_commit(); }
    }

    #pragma unroll
    for (int mt = 0; mt < 4; mt++) {
        #pragma unroll
        for (int nt = 0; nt < 4; nt++) {
            const long row0 = (long)(m0 + warpM * 64 + mt * 16 + g);
            const int col = n0 + warpN * 32 + nt * 8 + l4 * 2;
            float v0 = c[mt][nt][0], v1 = c[mt][nt][1];
            float v2 = c[mt][nt][2], v3 = c[mt][nt][3];
            if (ROUND) {
                v0 = cvt_tf32(v0); v1 = cvt_tf32(v1);
                v2 = cvt_tf32(v2); v3 = cvt_tf32(v3);
            }
            *(float2*)&C[row0 * N + col] = make_float2(v0, v1);
            *(float2*)&C[(row0 + 8) * N + col] = make_float2(v2, v3);
        }
    }
}

// ---------------------------------------------------------------------------
// Elementwise tf32 rounding (prep)
// ---------------------------------------------------------------------------
__global__ void cvt_tf32_kernel(const float* __restrict__ in, float* __restrict__ out,
                                int n4)
{
    int i = blockIdx.x * blockDim.x + threadIdx.x;
    if (i < n4) {
        float4 v = ((const float4*)in)[i];
        v.x = cvt_tf32(v.x); v.y = cvt_tf32(v.y);
        v.z = cvt_tf32(v.z); v.w = cvt_tf32(v.w);
        ((float4*)out)[i] = v;
    }
}

// ---------------------------------------------------------------------------
// Flash attention (causal) on tf32 mma.sync.
// Block: 128 q-rows, 4 warps (warp w owns rows [w*32, w*32+32)).
// KV tiles of 64 keys, cp.async double-buffered.
// SMEM: Ks[2][64][68], Vs[2][64][72], Ps[128][68] (Q staging, then P per warp).
// ---------------------------------------------------------------------------
#define FQT 128
#define FKT 64
#define KP 68
#define VP 72
#define PP 68
#define KS_OFF(s)  ((s) * 17408)
#define VS_OFF(s)  (34816 + (s) * 18432)
#define PS_OFF     71680
#define FLASH_SMEM_BYTES (PS_OFF + 128 * PP * 4)   // 106496
#define SC2 0.1803368801f   // (1/sqrt(64)) * log2(e)

__global__ __launch_bounds__(128)
void flash_tf32(const float* __restrict__ qkv, float* __restrict__ out)
{
    extern __shared__ char sm[];
    const uint32_t sb = smem_u32(sm);
    const int tid = threadIdx.x, w = tid >> 5, lane = tid & 31;
    const int g = lane >> 2, l4 = lane & 3;
    const int qt = (int)(gridDim.x - 1) - (int)blockIdx.x;   // heavy blocks first
    const int hh = blockIdx.y, b = blockIdx.z;
    const int q0 = qt * FQT;
    const int nkv = 2 * qt + 2;

    const float* qg = qkv + (long)b * SEQ * QKV3 + hh * HDIM;
    const float* kg = qg + HID;
    const float* vg = qg + 2 * HID;

    // --- Stage Q into PS region [128][PP] via cp.async (BOTH 64-row halves) ---
    {
        #pragma unroll
        for (int half = 0; half < 2; half++) {
            const int r = (tid >> 1) + half * 64;   // rows 0..127
            const int h2 = tid & 1;
            const float* src = qg + (long)(q0 + r) * QKV3 + h2 * 32;
            uint32_t dst = sb + PS_OFF + (uint32_t)(r * PP + h2 * 32) * 4;
            #pragma unroll
            for (int q = 0; q < 8; q++) cp16(dst + q * 16, src + q * 4);
        }
        cp_commit();
    }
    cp_wait0();
    __syncthreads();

    // --- Q fragments (row-major A): rows w*32+mt*16+g, cols ks*8+l4 ---
    uint32_t qa[2][8][4];
    #pragma unroll
    for (int mt = 0; mt < 2; mt++)
        #pragma unroll
        for (int ks = 0; ks < 8; ks++) {
            uint32_t base = sb + PS_OFF
                + (uint32_t)((w * 32 + mt * 16 + g) * PP + ks * 8 + l4) * 4;
            qa[mt][ks][0] = ldsu(base);
            qa[mt][ks][1] = ldsu(base + 8 * PP * 4);
            qa[mt][ks][2] = ldsu(base + 16);
            qa[mt][ks][3] = ldsu(base + 8 * PP * 4 + 16);
        }
    __syncthreads();

    auto issue_kv = [&](int kt2, int s) {
        const int k0 = kt2 * FKT;
        const int r = tid >> 1, h2 = tid & 1;   // 64 rows x 64 floats: exact
        const float* ksrc = kg + (long)(k0 + r) * QKV3 + h2 * 32;
        uint32_t kdst = sb + KS_OFF(s) + (uint32_t)(r * KP + h2 * 32) * 4;
        #pragma unroll
        for (int q = 0; q < 8; q++) cp16(kdst + q * 16, ksrc + q * 4);
        const float* vsrc = vg + (long)(k0 + r) * QKV3 + h2 * 32;
        uint32_t vdst = sb + VS_OFF(s) + (uint32_t)(r * VP + h2 * 32) * 4;
        #pragma unroll
        for (int q = 0; q < 8; q++) cp16(vdst + q * 16, vsrc + q * 4);
    };

    issue_kv(0, 0); cp_commit();
    if (nkv > 1) issue_kv(1, 1);
    cp_commit();

    float mA[2] = {-1e30f, -1e30f}, mB[2] = {-1e30f, -1e30f};
    float lA[2] = {0.f, 0.f}, lB[2] = {0.f, 0.f};
    float o[2][8][4];
    #pragma unroll
    for (int mt = 0; mt < 2; mt++)
        #pragma unroll
        for (int nt = 0; nt < 8; nt++)
            #pragma unroll
            for (int r = 0; r < 4; r++) o[mt][nt][r] = 0.f;

    #pragma unroll 1
    for (int kt = 0; kt < nkv; kt++) {
        const int s = kt & 1;
        if (kt + 2 < nkv) cp_wait1(); else cp_wait0();
        __syncthreads();

        const int k0 = kt * FKT;
        const int wrow0 = q0 + w * 32;
        const bool active = (k0 <= wrow0 + 31);
        const bool needmask = (k0 + FKT - 1 > wrow0);

        if (active) {
            const uint32_t kb = sb + KS_OFF(s);
            const uint32_t vb = sb + VS_OFF(s);

            #pragma unroll
            for (int mt = 0; mt < 2; mt++) {
                float cc[8][4];
                #pragma unroll
                for (int nt = 0; nt < 8; nt++)
                    #pragma unroll
                    for (int r = 0; r < 4; r++) cc[nt][r] = 0.f;

                // S = Q @ K^T : B[k][n] = K[n][k], from Ks [keys][dims]
                #pragma unroll
                for (int ks = 0; ks < 8; ks++) {
                    uint32_t bf[8][2];
                    #pragma unroll
                    for (int nt = 0; nt < 8; nt++) {
                        uint32_t a = kb + (uint32_t)((nt * 8 + g) * KP + ks * 8 + l4) * 4;
                        bf[nt][0] = ldsu(a);
                        bf[nt][1] = ldsu(a + 16);
                    }
                    #pragma unroll
                    for (int nt = 0; nt < 8; nt++)
                        mma_tf32(cc[nt], qa[mt][ks], bf[nt]);
                }

                const int rowA = wrow0 + mt * 16 + g;
                if (needmask) {
                    #pragma unroll
                    for (int nt = 0; nt < 8; nt++) {
                        const int colb = k0 + nt * 8 + 2 * l4;
                        if (colb     > rowA)     cc[nt][0] = -1e30f;
                        if (colb + 1 > rowA)     cc[nt][1] = -1e30f;
                        if (colb     > rowA + 8) cc[nt][2] = -1e30f;
                        if (colb + 1 > rowA + 8) cc[nt][3] = -1e30f;
                    }
                }

                // online softmax (rows A: regs 0,1 ; rows B: regs 2,3)
                float mxA = -1e30f, mxB = -1e30f;
                #pragma unroll
                for (int nt = 0; nt < 8; nt++) {
                    mxA = fmaxf(mxA, fmaxf(cc[nt][0], cc[nt][1]));
                    mxB = fmaxf(mxB, fmaxf(cc[nt][2], cc[nt][3]));
                }
                mxA = fmaxf(mxA, __shfl_xor_sync(0xffffffffu, mxA, 1));
                mxA = fmaxf(mxA, __shfl_xor_sync(0xffffffffu, mxA, 2));
                mxB = fmaxf(mxB, __shfl_xor_sync(0xffffffffu, mxB, 1));
                mxB = fmaxf(mxB, __shfl_xor_sync(0xffffffffu, mxB, 2));

                const float mAn = fmaxf(mA[mt], mxA);
                const float mBn = fmaxf(mB[mt], mxB);
                const float aAl = ex2f((mA[mt] - mAn) * SC2);
                const float aBl = ex2f((mB[mt] - mBn) * SC2);
                mA[mt] = mAn; mB[mt] = mBn;

                float sA = 0.f, sB = 0.f;
                const uint32_t pbase = sb + PS_OFF
                    + (uint32_t)((w * 32 + mt * 16 + g) * PP + 2 * l4) * 4;
                #pragma unroll
                for (int nt = 0; nt < 8; nt++) {
                    float p0 = ex2f((cc[nt][0] - mAn) * SC2);
                    float p1 = ex2f((cc[nt][1] - mAn) * SC2);
                    float p2 = ex2f((cc[nt][2] - mBn) * SC2);
                    float p3 = ex2f((cc[nt][3] - mBn) * SC2);
                    sA += p0 + p1; sB += p2 + p3;
                    sts2(pbase + nt * 32, cvt_tf32(p0), cvt_tf32(p1));
                    sts2(pbase + nt * 32 + 8 * PP * 4, cvt_tf32(p2), cvt_tf32(p3));
                }
                sA += __shfl_xor_sync(0xffffffffu, sA, 1);
                sA += __shfl_xor_sync(0xffffffffu, sA, 2);
                sB += __shfl_xor_sync(0xffffffffu, sB, 1);
                sB += __shfl_xor_sync(0xffffffffu, sB, 2);
                lA[mt] = lA[mt] * aAl + sA;
                lB[mt] = lB[mt] * aBl + sB;

                #pragma unroll
                for (int nt = 0; nt < 8; nt++) {
                    o[mt][nt][0] *= aAl; o[mt][nt][1] *= aAl;
                    o[mt][nt][2] *= aBl; o[mt][nt][3] *= aBl;
                }
            }
            __syncwarp();

            // O += P @ V : A = P from Ps, B[k][n] = V[k][n] from Vs [keys][dims]
            #pragma unroll
            for (int ks = 0; ks < 8; ks++) {
                uint32_t pa[2][4];
                #pragma unroll
                for (int mt = 0; mt < 2; mt++) {
                    uint32_t base = sb + PS_OFF
                        + (uint32_t)((w * 32 + mt * 16 + g) * PP + ks * 8 + l4) * 4;
                    pa[mt][0] = ldsu(base);
                    pa[mt][1] = ldsu(base + 8 * PP * 4);
                    pa[mt][2] = ldsu(base + 16);
                    pa[mt][3] = ldsu(base + 8 * PP * 4 + 16);
                }
                uint32_t bv[8][2];
                #pragma unroll
                for (int nt = 0; nt < 8; nt++) {
                    uint32_t a = vb + (uint32_t)((ks * 8 + l4) * VP + nt * 8 + g) * 4;
                    bv[nt][0] = ldsu(a);
                    bv[nt][1] = ldsu(a + 4 * VP * 4);
                }
                #pragma unroll
                for (int mt = 0; mt < 2; mt++)
                    #pragma unroll
                    for (int nt = 0; nt < 8; nt++)
                        mma_tf32(o[mt][nt], pa[mt], bv[nt]);
            }
        }

        __syncthreads();
        if (kt + 2 < nkv) { issue_kv(kt + 2, s); cp_commit(); }
    }

    // Epilogue: normalize, tf32-round, write [B,S,H]
    #pragma unroll
    for (int mt = 0; mt < 2; mt++) {
        const float invA = 1.f / lA[mt];
        const float invB = 1.f / lB[mt];
        const long rowA = (long)b * SEQ + q0 + w * 32 + mt * 16 + g;
        #pragma unroll
        for (int nt = 0; nt < 8; nt++) {
            const int col = hh * HDIM + nt * 8 + 2 * l4;
            *(float2*)&out[rowA * HID + col] =
                make_float2(cvt_tf32(o[mt][nt][0] * invA), cvt_tf32(o[mt][nt][1] * invA));
            *(float2*)&out[(rowA + 8) * HID + col] =
                make_float2(cvt_tf32(o[mt][nt][2] * invB), cvt_tf32(o[mt][nt][3] * invB));
        }
    }
}

// ---------------------------------------------------------------------------
// Launch
// ---------------------------------------------------------------------------
extern "C" void kernel_launch(void* const* d_in, const int* in_sizes, int n_in,
                              void* d_out, int out_size)
{
    const float* x     = (const float*)d_in[0];
    const float* w_qkv = (const float*)d_in[1];
    const float* w_out = (const float*)d_in[2];
    float* out = (float*)d_out;

    float *qkv, *attn, *xc, *wqkvc, *woutc;
    cudaGetSymbolAddress((void**)&qkv, g_qkv);
    cudaGetSymbolAddress((void**)&attn, g_attn);
    cudaGetSymbolAddress((void**)&xc, g_xc);
    cudaGetSymbolAddress((void**)&wqkvc, g_wqkvc);
    cudaGetSymbolAddress((void**)&woutc, g_woutc);

    const int M = BATCH * SEQ;   // 8192

    // 0) tf32-round GEMM inputs
    {
        int n4 = (M * HID) / 4;
        cvt_tf32_kernel<<<(n4 + 255) / 256, 256>>>(x, xc, n4);
        n4 = (KDIM * QKV3) / 4;
        cvt_tf32_kernel<<<(n4 + 255) / 256, 256>>>(w_qkv, wqkvc, n4);
        n4 = (KDIM * HID) / 4;
        cvt_tf32_kernel<<<(n4 + 255) / 256, 256>>>(w_out, woutc, n4);
    }

    cudaFuncSetAttribute(gemm_tf32<true>, cudaFuncAttributeMaxDynamicSharedMemorySize,
                         GEMM_SMEM_BYTES);
    cudaFuncSetAttribute(gemm_tf32<false>, cudaFuncAttributeMaxDynamicSharedMemorySize,
                         GEMM_SMEM_BYTES);
    cudaFuncSetAttribute(flash_tf32, cudaFuncAttributeMaxDynamicSharedMemorySize,
                         FLASH_SMEM_BYTES);

    // 1) QKV projection (output tf32-rounded for the attention mma)
    gemm_tf32<true><<<dim3(QKV3 / 128, M / 128), 256, GEMM_SMEM_BYTES>>>(
        xc, wqkvc, qkv, M, QKV3, KDIM);

    // 2) Causal flash attention on tensor cores
    flash_tf32<<<dim3(SEQ / FQT, NHEAD, BATCH), 128, FLASH_SMEM_BYTES>>>(qkv, attn);

    // 3) Output projection
    gemm_tf32<false><<<dim3(HID / 128, M / 128), 256, GEMM_SMEM_BYTES>>>(
        attn, woutc, out, M, HID, KDIM);
}

// round 7
// speedup vs baseline: 2.6120x; 1.0263x over previous
#include <cuda_runtime.h>
#include <cuda_bf16.h>
#include <cstdint>

// Problem constants
#define BATCH 4
#define SEQ   2048
#define HID   768
#define NHEAD 12
#define HDIM  64
#define QKV3  2304
#define KDIM  768

// Scratch (allocation-free: __device__ globals)
__device__ float g_qkv[(long)BATCH * SEQ * QKV3];    // [B,S,3H] tf32-rounded
__device__ float g_attn[(long)BATCH * SEQ * HID];    // [B,S,H]  tf32-rounded
__device__ float g_xc[(long)BATCH * SEQ * HID];      // x, tf32-rounded
__device__ float g_wqkvc[(long)KDIM * QKV3];         // w_qkv tf32-rounded [K][N]
__device__ float g_woutc[(long)KDIM * HID];          // w_out tf32-rounded [K][N]

// ---------------------------------------------------------------------------
// Helpers
// ---------------------------------------------------------------------------
__device__ __forceinline__ uint32_t smem_u32(const void* p) {
    uint32_t a;
    asm("{ .reg .u64 t; cvta.to.shared.u64 t, %1; cvt.u32.u64 %0, t; }" : "=r"(a) : "l"(p));
    return a;
}
__device__ __forceinline__ float cvt_tf32(float x) {
    float r;
    asm("cvt.rna.tf32.f32 %0, %1;" : "=f"(r) : "f"(x));
    return r;
}
__device__ __forceinline__ float ex2f(float x) {
    float r;
    asm("ex2.approx.f32 %0, %1;" : "=f"(r) : "f"(x));
    return r;
}
__device__ __forceinline__ void cp16(uint32_t dst, const void* src) {
    asm volatile("cp.async.cg.shared.global [%0], [%1], 16;" :: "r"(dst), "l"(src) : "memory");
}
__device__ __forceinline__ void cp_commit() {
    asm volatile("cp.async.commit_group;" ::: "memory");
}
__device__ __forceinline__ void cp_wait1() {
    asm volatile("cp.async.wait_group 1;" ::: "memory");
}
__device__ __forceinline__ void cp_wait0() {
    asm volatile("cp.async.wait_group 0;" ::: "memory");
}
__device__ __forceinline__ uint32_t ldsu(uint32_t addr) {
    uint32_t v;
    asm volatile("ld.shared.b32 %0, [%1];" : "=r"(v) : "r"(addr));
    return v;
}
__device__ __forceinline__ void sts2(uint32_t addr, float x, float y) {
    asm volatile("st.shared.v2.f32 [%0], {%1, %2};" :: "r"(addr), "f"(x), "f"(y) : "memory");
}
__device__ __forceinline__ void mma_tf32(float* c, const uint32_t* a, const uint32_t* b) {
    asm volatile(
        "mma.sync.aligned.m16n8k8.row.col.f32.tf32.tf32.f32 "
        "{%0,%1,%2,%3}, {%4,%5,%6,%7}, {%8,%9}, {%0,%1,%2,%3};"
        : "+f"(c[0]), "+f"(c[1]), "+f"(c[2]), "+f"(c[3])
        : "r"(a[0]), "r"(a[1]), "r"(a[2]), "r"(a[3]), "r"(b[0]), "r"(b[1]));
}

// ---------------------------------------------------------------------------
// tf32 mma.sync GEMM, v2: 3-stage cp.async pipeline (1 sync/chunk) +
// register double-buffered fragments. ROUND: tf32-round output (for qkv).
// ---------------------------------------------------------------------------
#define AS_BYTES (128 * 36 * 4)   // 18432, A row pitch 144B
#define BS_BYTES (32 * 132 * 4)   // 16896, B row pitch 528B
#define STAGE_BYTES (AS_BYTES + BS_BYTES)
#define GEMM_SMEM_BYTES (3 * STAGE_BYTES)   // 105984

template <bool ROUND>
__global__ __launch_bounds__(256, 2)
void gemm_tf32(const float* __restrict__ A, const float* __restrict__ B,
               float* __restrict__ C, int M, int N, int K)
{
    extern __shared__ char smem[];
    const uint32_t sb = smem_u32(smem);

    const int tid = threadIdx.x;
    const int wid = tid >> 5, lane = tid & 31;
    const int g = lane >> 2, l4 = lane & 3;
    const int warpM = wid >> 2, warpN = wid & 3;
    const int m0 = blockIdx.y * 128, n0 = blockIdx.x * 128;

    const int ar = tid >> 1;
    const int ah = (tid & 1) * 64;
    const int bkr = tid >> 3;
    const int bseg = (tid & 7) * 64;

    const float* Ag = A + (long)(m0 + ar) * K;
    const float* Bg = B + n0;
    const int nch = K / 32;

    float c[4][4][4];
    #pragma unroll
    for (int mt = 0; mt < 4; mt++)
        #pragma unroll
        for (int nt = 0; nt < 4; nt++)
            #pragma unroll
            for (int r = 0; r < 4; r++) c[mt][nt][r] = 0.f;

    auto issue = [&](int chunk, int s) {
        const int k0 = chunk * 32;
        const uint32_t stage = sb + (uint32_t)s * STAGE_BYTES;
        const float* asrc = Ag + k0 + (ah >> 2);
        uint32_t adst = stage + ar * 144 + ah;
        #pragma unroll
        for (int q = 0; q < 4; q++) cp16(adst + q * 16, asrc + q * 4);
        const float* bsrc = Bg + (long)(k0 + bkr) * N + (bseg >> 2);
        uint32_t bdst = stage + AS_BYTES + bkr * 528 + bseg;
        #pragma unroll
        for (int q = 0; q < 4; q++) cp16(bdst + q * 16, bsrc + q * 4);
    };

    issue(0, 0); cp_commit();
    issue(1, 1); cp_commit();

    // per-warp fragment base offsets (within a stage)
    const uint32_t aoff = (uint32_t)((warpM * 64 + g) * 144 + l4 * 4);
    const uint32_t boff = (uint32_t)(AS_BYTES + l4 * 528 + (warpN * 32 + g) * 4);

    uint32_t af[2][4][4], bf[2][4][2];

    #pragma unroll 1
    for (int i = 0; i < nch; i++) {
        const int s = i - (i / 3) * 3;
        if (i + 1 < nch) cp_wait1(); else cp_wait0();
        __syncthreads();
        if (i + 2 < nch) { issue(i + 2, (i + 2) % 3); cp_commit(); }

        const uint32_t abase = sb + (uint32_t)s * STAGE_BYTES + aoff;
        const uint32_t bbase = sb + (uint32_t)s * STAGE_BYTES + boff;

        // load frags for ks=0 into buf 0
        #pragma unroll
        for (int mt = 0; mt < 4; mt++) {
            const uint32_t a = abase + mt * (16 * 144);
            af[0][mt][0] = ldsu(a);
            af[0][mt][1] = ldsu(a + 8 * 144);
            af[0][mt][2] = ldsu(a + 16);
            af[0][mt][3] = ldsu(a + 8 * 144 + 16);
        }
        #pragma unroll
        for (int nt = 0; nt < 4; nt++) {
            const uint32_t a = bbase + nt * 32;
            bf[0][nt][0] = ldsu(a);
            bf[0][nt][1] = ldsu(a + 4 * 528);
        }

        #pragma unroll
        for (int ks = 0; ks < 4; ks++) {
            const int cur = ks & 1, nxt = cur ^ 1;
            if (ks < 3) {   // prefetch ks+1 fragments while MMAs of ks issue
                #pragma unroll
                for (int mt = 0; mt < 4; mt++) {
                    const uint32_t a = abase + mt * (16 * 144) + (ks + 1) * 32;
                    af[nxt][mt][0] = ldsu(a);
                    af[nxt][mt][1] = ldsu(a + 8 * 144);
                    af[nxt][mt][2] = ldsu(a + 16);
                    af[nxt][mt][3] = ldsu(a + 8 * 144 + 16);
                }
                #pragma unroll
                for (int nt = 0; nt < 4; nt++) {
                    const uint32_t a = bbase + (ks + 1) * (8 * 528) + nt * 32;
                    bf[nxt][nt][0] = ldsu(a);
                    bf[nxt][nt][1] = ldsu(a + 4 * 528);
                }
            }
            #pragma unroll
            for (int mt = 0; mt < 4; mt++)
                #pragma unroll
                for (int nt = 0; nt < 4; nt++)
                    mma_tf32(c[mt][nt], af[cur][mt], bf[cur][nt]);
        }
    }

    #pragma unroll
    for (int mt = 0; mt < 4; mt++) {
        #pragma unroll
        for (int nt = 0; nt < 4; nt++) {
            const long row0 = (long)(m0 + warpM * 64 + mt * 16 + g);
            const int col = n0 + warpN * 32 + nt * 8 + l4 * 2;
            float v0 = c[mt][nt][0], v1 = c[mt][nt][1];
            float v2 = c[mt][nt][2], v3 = c[mt][nt][3];
            if (ROUND) {
                v0 = cvt_tf32(v0); v1 = cvt_tf32(v1);
                v2 = cvt_tf32(v2); v3 = cvt_tf32(v3);
            }
            *(float2*)&C[row0 * N + col] = make_float2(v0, v1);
            *(float2*)&C[(row0 + 8) * N + col] = make_float2(v2, v3);
        }
    }
}

// ---------------------------------------------------------------------------
// Elementwise tf32 rounding (prep)
// ---------------------------------------------------------------------------
__global__ void cvt_tf32_kernel(const float* __restrict__ in, float* __restrict__ out,
                                int n4)
{
    int i = blockIdx.x * blockDim.x + threadIdx.x;
    if (i < n4) {
        float4 v = ((const float4*)in)[i];
        v.x = cvt_tf32(v.x); v.y = cvt_tf32(v.y);
        v.z = cvt_tf32(v.z); v.w = cvt_tf32(v.w);
        ((float4*)out)[i] = v;
    }
}

// ---------------------------------------------------------------------------
// Flash attention (causal) on tf32 mma.sync — UNCHANGED from R6 (passing).
// ---------------------------------------------------------------------------
#define FQT 128
#define FKT 64
#define KP 68
#define VP 72
#define PP 68
#define KS_OFF(s)  ((s) * 17408)
#define VS_OFF(s)  (34816 + (s) * 18432)
#define PS_OFF     71680
#define FLASH_SMEM_BYTES (PS_OFF + 128 * PP * 4)   // 106496
#define SC2 0.1803368801f   // (1/sqrt(64)) * log2(e)

__global__ __launch_bounds__(128)
void flash_tf32(const float* __restrict__ qkv, float* __restrict__ out)
{
    extern __shared__ char sm[];
    const uint32_t sb = smem_u32(sm);
    const int tid = threadIdx.x, w = tid >> 5, lane = tid & 31;
    const int g = lane >> 2, l4 = lane & 3;
    const int qt = (int)(gridDim.x - 1) - (int)blockIdx.x;   // heavy blocks first
    const int hh = blockIdx.y, b = blockIdx.z;
    const int q0 = qt * FQT;
    const int nkv = 2 * qt + 2;

    const float* qg = qkv + (long)b * SEQ * QKV3 + hh * HDIM;
    const float* kg = qg + HID;
    const float* vg = qg + 2 * HID;

    // --- Stage Q into PS region [128][PP] via cp.async (both 64-row halves) ---
    {
        #pragma unroll
        for (int half = 0; half < 2; half++) {
            const int r = (tid >> 1) + half * 64;
            const int h2 = tid & 1;
            const float* src = qg + (long)(q0 + r) * QKV3 + h2 * 32;
            uint32_t dst = sb + PS_OFF + (uint32_t)(r * PP + h2 * 32) * 4;
            #pragma unroll
            for (int q = 0; q < 8; q++) cp16(dst + q * 16, src + q * 4);
        }
        cp_commit();
    }
    cp_wait0();
    __syncthreads();

    uint32_t qa[2][8][4];
    #pragma unroll
    for (int mt = 0; mt < 2; mt++)
        #pragma unroll
        for (int ks = 0; ks < 8; ks++) {
            uint32_t base = sb + PS_OFF
                + (uint32_t)((w * 32 + mt * 16 + g) * PP + ks * 8 + l4) * 4;
            qa[mt][ks][0] = ldsu(base);
            qa[mt][ks][1] = ldsu(base + 8 * PP * 4);
            qa[mt][ks][2] = ldsu(base + 16);
            qa[mt][ks][3] = ldsu(base + 8 * PP * 4 + 16);
        }
    __syncthreads();

    auto issue_kv = [&](int kt2, int s) {
        const int k0 = kt2 * FKT;
        const int r = tid >> 1, h2 = tid & 1;
        const float* ksrc = kg + (long)(k0 + r) * QKV3 + h2 * 32;
        uint32_t kdst = sb + KS_OFF(s) + (uint32_t)(r * KP + h2 * 32) * 4;
        #pragma unroll
        for (int q = 0; q < 8; q++) cp16(kdst + q * 16, ksrc + q * 4);
        const float* vsrc = vg + (long)(k0 + r) * QKV3 + h2 * 32;
        uint32_t vdst = sb + VS_OFF(s) + (uint32_t)(r * VP + h2 * 32) * 4;
        #pragma unroll
        for (int q = 0; q < 8; q++) cp16(vdst + q * 16, vsrc + q * 4);
    };

    issue_kv(0, 0); cp_commit();
    if (nkv > 1) issue_kv(1, 1);
    cp_commit();

    float mA[2] = {-1e30f, -1e30f}, mB[2] = {-1e30f, -1e30f};
    float lA[2] = {0.f, 0.f}, lB[2] = {0.f, 0.f};
    float o[2][8][4];
    #pragma unroll
    for (int mt = 0; mt < 2; mt++)
        #pragma unroll
        for (int nt = 0; nt < 8; nt++)
            #pragma unroll
            for (int r = 0; r < 4; r++) o[mt][nt][r] = 0.f;

    #pragma unroll 1
    for (int kt = 0; kt < nkv; kt++) {
        const int s = kt & 1;
        if (kt + 2 < nkv) cp_wait1(); else cp_wait0();
        __syncthreads();

        const int k0 = kt * FKT;
        const int wrow0 = q0 + w * 32;
        const bool active = (k0 <= wrow0 + 31);
        const bool needmask = (k0 + FKT - 1 > wrow0);

        if (active) {
            const uint32_t kb = sb + KS_OFF(s);
            const uint32_t vb = sb + VS_OFF(s);

            #pragma unroll
            for (int mt = 0; mt < 2; mt++) {
                float cc[8][4];
                #pragma unroll
                for (int nt = 0; nt < 8; nt++)
                    #pragma unroll
                    for (int r = 0; r < 4; r++) cc[nt][r] = 0.f;

                #pragma unroll
                for (int ks = 0; ks < 8; ks++) {
                    uint32_t bfr[8][2];
                    #pragma unroll
                    for (int nt = 0; nt < 8; nt++) {
                        uint32_t a = kb + (uint32_t)((nt * 8 + g) * KP + ks * 8 + l4) * 4;
                        bfr[nt][0] = ldsu(a);
                        bfr[nt][1] = ldsu(a + 16);
                    }
                    #pragma unroll
                    for (int nt = 0; nt < 8; nt++)
                        mma_tf32(cc[nt], qa[mt][ks], bfr[nt]);
                }

                const int rowA = wrow0 + mt * 16 + g;
                if (needmask) {
                    #pragma unroll
                    for (int nt = 0; nt < 8; nt++) {
                        const int colb = k0 + nt * 8 + 2 * l4;
                        if (colb     > rowA)     cc[nt][0] = -1e30f;
                        if (colb + 1 > rowA)     cc[nt][1] = -1e30f;
                        if (colb     > rowA + 8) cc[nt][2] = -1e30f;
                        if (colb + 1 > rowA + 8) cc[nt][3] = -1e30f;
                    }
                }

                float mxA = -1e30f, mxB = -1e30f;
                #pragma unroll
                for (int nt = 0; nt < 8; nt++) {
                    mxA = fmaxf(mxA, fmaxf(cc[nt][0], cc[nt][1]));
                    mxB = fmaxf(mxB, fmaxf(cc[nt][2], cc[nt][3]));
                }
                mxA = fmaxf(mxA, __shfl_xor_sync(0xffffffffu, mxA, 1));
                mxA = fmaxf(mxA, __shfl_xor_sync(0xffffffffu, mxA, 2));
                mxB = fmaxf(mxB, __shfl_xor_sync(0xffffffffu, mxB, 1));
                mxB = fmaxf(mxB, __shfl_xor_sync(0xffffffffu, mxB, 2));

                const float mAn = fmaxf(mA[mt], mxA);
                const float mBn = fmaxf(mB[mt], mxB);
                const float aAl = ex2f((mA[mt] - mAn) * SC2);
                const float aBl = ex2f((mB[mt] - mBn) * SC2);
                mA[mt] = mAn; mB[mt] = mBn;

                float sA = 0.f, sB = 0.f;
                const uint32_t pbase = sb + PS_OFF
                    + (uint32_t)((w * 32 + mt * 16 + g) * PP + 2 * l4) * 4;
                #pragma unroll
                for (int nt = 0; nt < 8; nt++) {
                    float p0 = ex2f((cc[nt][0] - mAn) * SC2);
                    float p1 = ex2f((cc[nt][1] - mAn) * SC2);
                    float p2 = ex2f((cc[nt][2] - mBn) * SC2);
                    float p3 = ex2f((cc[nt][3] - mBn) * SC2);
                    sA += p0 + p1; sB += p2 + p3;
                    sts2(pbase + nt * 32, cvt_tf32(p0), cvt_tf32(p1));
                    sts2(pbase + nt * 32 + 8 * PP * 4, cvt_tf32(p2), cvt_tf32(p3));
                }
                sA += __shfl_xor_sync(0xffffffffu, sA, 1);
                sA += __shfl_xor_sync(0xffffffffu, sA, 2);
                sB += __shfl_xor_sync(0xffffffffu, sB, 1);
                sB += __shfl_xor_sync(0xffffffffu, sB, 2);
                lA[mt] = lA[mt] * aAl + sA;
                lB[mt] = lB[mt] * aBl + sB;

                #pragma unroll
                for (int nt = 0; nt < 8; nt++) {
                    o[mt][nt][0] *= aAl; o[mt][nt][1] *= aAl;
                    o[mt][nt][2] *= aBl; o[mt][nt][3] *= aBl;
                }
            }
            __syncwarp();

            #pragma unroll
            for (int ks = 0; ks < 8; ks++) {
                uint32_t pa[2][4];
                #pragma unroll
                for (int mt = 0; mt < 2; mt++) {
                    uint32_t base = sb + PS_OFF
                        + (uint32_t)((w * 32 + mt * 16 + g) * PP + ks * 8 + l4) * 4;
                    pa[mt][0] = ldsu(base);
                    pa[mt][1] = ldsu(base + 8 * PP * 4);
                    pa[mt][2] = ldsu(base + 16);
                    pa[mt][3] = ldsu(base + 8 * PP * 4 + 16);
                }
                uint32_t bv[8][2];
                #pragma unroll
                for (int nt = 0; nt < 8; nt++) {
                    uint32_t a = vb + (uint32_t)((ks * 8 + l4) * VP + nt * 8 + g) * 4;
                    bv[nt][0] = ldsu(a);
                    bv[nt][1] = ldsu(a + 4 * VP * 4);
                }
                #pragma unroll
                for (int mt = 0; mt < 2; mt++)
                    #pragma unroll
                    for (int nt = 0; nt < 8; nt++)
                        mma_tf32(o[mt][nt], pa[mt], bv[nt]);
            }
        }

        __syncthreads();
        if (kt + 2 < nkv) { issue_kv(kt + 2, s); cp_commit(); }
    }

    #pragma unroll
    for (int mt = 0; mt < 2; mt++) {
        const float invA = 1.f / lA[mt];
        const float invB = 1.f / lB[mt];
        const long rowA = (long)b * SEQ + q0 + w * 32 + mt * 16 + g;
        #pragma unroll
        for (int nt = 0; nt < 8; nt++) {
            const int col = hh * HDIM + nt * 8 + 2 * l4;
            *(float2*)&out[rowA * HID + col] =
                make_float2(cvt_tf32(o[mt][nt][0] * invA), cvt_tf32(o[mt][nt][1] * invA));
            *(float2*)&out[(rowA + 8) * HID + col] =
                make_float2(cvt_tf32(o[mt][nt][2] * invB), cvt_tf32(o[mt][nt][3] * invB));
        }
    }
}

// ---------------------------------------------------------------------------
// Launch
// ---------------------------------------------------------------------------
extern "C" void kernel_launch(void* const* d_in, const int* in_sizes, int n_in,
                              void* d_out, int out_size)
{
    const float* x     = (const float*)d_in[0];
    const float* w_qkv = (const float*)d_in[1];
    const float* w_out = (const float*)d_in[2];
    float* out = (float*)d_out;

    float *qkv, *attn, *xc, *wqkvc, *woutc;
    cudaGetSymbolAddress((void**)&qkv, g_qkv);
    cudaGetSymbolAddress((void**)&attn, g_attn);
    cudaGetSymbolAddress((void**)&xc, g_xc);
    cudaGetSymbolAddress((void**)&wqkvc, g_wqkvc);
    cudaGetSymbolAddress((void**)&woutc, g_woutc);

    const int M = BATCH * SEQ;   // 8192

    // 0) tf32-round GEMM inputs
    {
        int n4 = (M * HID) / 4;
        cvt_tf32_kernel<<<(n4 + 255) / 256, 256>>>(x, xc, n4);
        n4 = (KDIM * QKV3) / 4;
        cvt_tf32_kernel<<<(n4 + 255) / 256, 256>>>(w_qkv, wqkvc, n4);
        n4 = (KDIM * HID) / 4;
        cvt_tf32_kernel<<<(n4 + 255) / 256, 256>>>(w_out, woutc, n4);
    }

    cudaFuncSetAttribute(gemm_tf32<true>, cudaFuncAttributeMaxDynamicSharedMemorySize,
                         GEMM_SMEM_BYTES);
    cudaFuncSetAttribute(gemm_tf32<false>, cudaFuncAttributeMaxDynamicSharedMemorySize,
                         GEMM_SMEM_BYTES);
    cudaFuncSetAttribute(flash_tf32, cudaFuncAttributeMaxDynamicSharedMemorySize,
                         FLASH_SMEM_BYTES);

    // 1) QKV projection (output tf32-rounded for the attention mma)
    gemm_tf32<true><<<dim3(QKV3 / 128, M / 128), 256, GEMM_SMEM_BYTES>>>(
        xc, wqkvc, qkv, M, QKV3, KDIM);

    // 2) Causal flash attention on tensor cores
    flash_tf32<<<dim3(SEQ / FQT, NHEAD, BATCH), 128, FLASH_SMEM_BYTES>>>(qkv, attn);

    // 3) Output projection
    gemm_tf32<false><<<dim3(HID / 128, M / 128), 256, GEMM_SMEM_BYTES>>>(
        attn, woutc, out, M, HID, KDIM);
}